// round 4
// baseline (speedup 1.0000x reference)
#include <cuda_runtime.h>
#include <math.h>

#define WPB 8
#define THREADS 256
#define WPFL 8192                 // one packed weight buffer (floats)
#define SSTR 4416                 // per-sample scratch floats: 64 bc | 2048 act1 | 2048 act2 | 256 act3

__device__ __forceinline__ void ffma2(unsigned long long& d,
                                      unsigned long long a,
                                      unsigned long long b) {
    asm("fma.rn.f32x2 %0, %1, %2, %0;" : "+l"(d) : "l"(a), "l"(b));
}
__device__ __forceinline__ float2 upk2(unsigned long long v) {
    float lo, hi;
    asm("mov.b64 {%0, %1}, %2;" : "=f"(lo), "=f"(hi) : "l"(v));
    return make_float2(lo, hi);
}

__global__ __launch_bounds__(THREADS, 1)
void NTC_30202210025785_kernel(
    const int*   __restrict__ gi, const int* __restrict__ gj, const int* __restrict__ gk,
    const float* __restrict__ A,  const float* __restrict__ Bm, const float* __restrict__ Cm,
    const float* __restrict__ W0, const float* __restrict__ b0,
    const float* __restrict__ W1, const float* __restrict__ b1,
    const float* __restrict__ W2, const float* __restrict__ b2,
    const float* __restrict__ W3, const float* __restrict__ b3,
    const float* __restrict__ fcw, const float* __restrict__ fcb,
    float* __restrict__ out)
{
    extern __shared__ float smem[];
    float* Wp1 = smem;            // holds packed W1; later repacked with W3
    float* Wp2 = smem + WPFL;     // packed W2
    float* sampBase = smem + 2 * WPFL;

    const int tid = threadIdx.x;

    // ---- pack W1 / W2 into smem: float4 index (half*32 + c)*32 + g,
    //      where float4 = W[g][c][half*4 .. half*4+3] (contiguous in gmem) ----
    {
        const float4* w1v = (const float4*)W1;
        const float4* w2v = (const float4*)W2;
        float4* p1 = (float4*)Wp1;
        float4* p2 = (float4*)Wp2;
        for (int e = tid; e < 2048; e += THREADS) {
            int gg = e >> 6, rem = e & 63, cc_ = rem >> 1, hf = rem & 1;
            int dst = (hf * 32 + cc_) * 32 + gg;
            p1[dst] = w1v[e];
            p2[dst] = w2v[e];
        }
    }
    __syncthreads();

    const int warp = tid >> 5;
    const int lane = tid & 31;
    const int g = lane;
    const int sample = blockIdx.x * WPB + warp;

    float* sbc  = sampBase + warp * SSTR;      // b[16], c[16]
    float* act1 = sbc + 64;                    // 8 rows x 256 (k = dd*128 + c*4 + hh*2+ww)
    float* act2 = act1 + 2048;                 // 8 rows x 256 (k = dd2*128 + g*4 + hh2*2+ww2)
    float* act3 = act2 + 2048;                 // 256        (k = (p2>>2)*128 + g*4 + (p2&3))
    ulonglong2* act1u = (ulonglong2*)act1;
    ulonglong2* act2u = (ulonglong2*)act2;
    ulonglong2* act3u = (ulonglong2*)act3;

    // ---- per-sample factors: a in registers, b/c in smem ----
    float ar[16];
    {
        const int ii = gi[sample];
        const int jj = gj[sample];
        const int kk = gk[sample];
        const float4* Av = (const float4*)(A + ii * 16);
#pragma unroll
        for (int q = 0; q < 4; q++) {
            float4 v = Av[q];
            ar[4 * q + 0] = v.x; ar[4 * q + 1] = v.y; ar[4 * q + 2] = v.z; ar[4 * q + 3] = v.w;
        }
        if (lane < 16) {
            sbc[lane]      = Bm[jj * 16 + lane];
            sbc[16 + lane] = Cm[kk * 16 + lane];
        }
    }
    __syncwarp();

    // per-lane conv0 taps + biases
    float w0r[8];
    {
        const float4* w0v = (const float4*)W0;
        float4 wa = w0v[g * 2], wb = w0v[g * 2 + 1];
        w0r[0] = wa.x; w0r[1] = wa.y; w0r[2] = wa.z; w0r[3] = wa.w;
        w0r[4] = wb.x; w0r[5] = wb.y; w0r[6] = wb.z; w0r[7] = wb.w;
    }
    const float bias0 = b0[g];
    const float bias1 = b1[g];
    const float bias2 = b2[g];
    const float bias3 = b3[g];
    const float fcwg  = fcw[g];

    const ulonglong2* wv1 = ((const ulonglong2*)Wp1) + g;
    const ulonglong2* wv2 = ((const ulonglong2*)Wp2) + g;

    // ================= conv0 + conv1: 8 passes, 8 outputs per weight pass =========
    for (int pass = 0; pass < 8; pass++) {
        const int h1  = pass >> 1;
        const int w1p = pass & 1;

        // --- conv0: build 8 im2col rows (r = w1s*4 + d1) ---
#pragma unroll
        for (int w1s = 0; w1s < 2; w1s++) {
            const int w1 = w1p * 2 + w1s;
            float bb[4], cc[4];
#pragma unroll
            for (int q = 0; q < 4; q++) { bb[q] = sbc[4 * h1 + q]; cc[q] = sbc[16 + 4 * w1 + q]; }
            float bcp[16];
#pragma unroll
            for (int i0 = 0; i0 < 4; i0++)
#pragma unroll
                for (int j0 = 0; j0 < 4; j0++)
                    bcp[i0 * 4 + j0] = bb[i0] * cc[j0];

            float u0[4], u1[4];
#pragma unroll
            for (int hh = 0; hh < 2; hh++)
#pragma unroll
                for (int ww = 0; ww < 2; ww++) {
                    const int q = hh * 2 + ww;
                    float v0, v1;
                    v0 =      w0r[0] * bcp[(2 * hh) * 4 + 2 * ww];
                    v0 = fmaf(w0r[1],  bcp[(2 * hh) * 4 + 2 * ww + 1], v0);
                    v0 = fmaf(w0r[2],  bcp[(2 * hh + 1) * 4 + 2 * ww], v0);
                    v0 = fmaf(w0r[3],  bcp[(2 * hh + 1) * 4 + 2 * ww + 1], v0);
                    v1 =      w0r[4] * bcp[(2 * hh) * 4 + 2 * ww];
                    v1 = fmaf(w0r[5],  bcp[(2 * hh) * 4 + 2 * ww + 1], v1);
                    v1 = fmaf(w0r[6],  bcp[(2 * hh + 1) * 4 + 2 * ww], v1);
                    v1 = fmaf(w0r[7],  bcp[(2 * hh + 1) * 4 + 2 * ww + 1], v1);
                    u0[q] = v0; u1[q] = v1;
                }

#pragma unroll
            for (int d1 = 0; d1 < 4; d1++) {
                const float a0 = ar[4 * d1 + 0], a1 = ar[4 * d1 + 1];
                const float a2 = ar[4 * d1 + 2], a3 = ar[4 * d1 + 3];
                float y[8];
#pragma unroll
                for (int q = 0; q < 4; q++) {
                    y[q]     = fmaxf(fmaf(u1[q], a1, fmaf(u0[q], a0, bias0)), 0.f);
                    y[4 + q] = fmaxf(fmaf(u1[q], a3, fmaf(u0[q], a2, bias0)), 0.f);
                }
                const int r = w1s * 4 + d1;
                ((float4*)act1)[r * 64 + g]      = make_float4(y[0], y[1], y[2], y[3]); // dd=0
                ((float4*)act1)[r * 64 + 32 + g] = make_float4(y[4], y[5], y[6], y[7]); // dd=1
            }
        }
        __syncwarp();

        // --- conv1: 8 outputs per lane in one pass over W1 (packed f32x2) ---
        unsigned long long acc[8];
#pragma unroll
        for (int r = 0; r < 8; r++) acc[r] = 0ull;
#pragma unroll 4
        for (int kb = 0; kb < 64; kb++) {
            const ulonglong2 w = wv1[kb * 32];
#pragma unroll
            for (int r = 0; r < 8; r++) {
                const ulonglong2 x = act1u[r * 64 + kb];
                ffma2(acc[r], w.x, x.x);
                ffma2(acc[r], w.y, x.y);
            }
        }

        // --- relu + scatter into conv2 im2col ---
        const int h2 = h1 >> 1, hh2 = h1 & 1;
#pragma unroll
        for (int r = 0; r < 8; r++) {
            const int w1s = r >> 2, d1 = r & 3;
            const int d2 = d1 >> 1, dd2 = d1 & 1;
            const float2 p = upk2(acc[r]);
            const float s = fmaxf(p.x + p.y + bias1, 0.f);
            const int p2 = d2 * 4 + h2 * 2 + w1p;          // w2 == w1p
            act2[p2 * 256 + dd2 * 128 + g * 4 + hh2 * 2 + w1s] = s;
        }
        __syncwarp();
    }

    // ---- repack Wp1 <- W3 (conv1 done block-wide) ----
    __syncthreads();
    {
        const float4* w3v = (const float4*)W3;
        float4* p1 = (float4*)Wp1;
        for (int e = tid; e < 2048; e += THREADS) {
            int gg = e >> 6, rem = e & 63, cc_ = rem >> 1, hf = rem & 1;
            p1[(hf * 32 + cc_) * 32 + gg] = w3v[e];
        }
    }
    __syncthreads();

    // ================= conv2: all 8 positions in one weight pass =================
    {
        unsigned long long q[8];
#pragma unroll
        for (int p2 = 0; p2 < 8; p2++) q[p2] = 0ull;
#pragma unroll 2
        for (int kb = 0; kb < 64; kb++) {
            const ulonglong2 w = wv2[kb * 32];
#pragma unroll
            for (int p2 = 0; p2 < 8; p2++) {
                const ulonglong2 x = act2u[p2 * 64 + kb];
                ffma2(q[p2], w.x, x.x);
                ffma2(q[p2], w.y, x.y);
            }
        }
        float y2[8];
#pragma unroll
        for (int p2 = 0; p2 < 8; p2++) {
            const float2 p = upk2(q[p2]);
            y2[p2] = fmaxf(p.x + p.y + bias2, 0.f);
        }
        ((float4*)act3)[g]      = make_float4(y2[0], y2[1], y2[2], y2[3]); // half=0
        ((float4*)act3)[32 + g] = make_float4(y2[4], y2[5], y2[6], y2[7]); // half=1
    }
    __syncwarp();

    // ================= conv3 + fc + sigmoid =================
    {
        const ulonglong2* wv3 = ((const ulonglong2*)Wp1) + g;
        unsigned long long e0 = 0ull, e1 = 0ull;
#pragma unroll 8
        for (int kb = 0; kb < 64; kb++) {
            const ulonglong2 w = wv3[kb * 32];
            const ulonglong2 x = act3u[kb];
            ffma2(e0, w.x, x.x);
            ffma2(e1, w.y, x.y);
        }
        const float2 pa = upk2(e0), pb = upk2(e1);
        const float y3 = fmaxf((pa.x + pa.y) + (pb.x + pb.y) + bias3, 0.f);
        float v = y3 * fcwg;
#pragma unroll
        for (int off = 16; off > 0; off >>= 1)
            v += __shfl_xor_sync(0xffffffffu, v, off);
        if (lane == 0) {
            const float z = v + fcb[0];
            out[sample] = 1.0f / (1.0f + expf(-z));
        }
    }
}

extern "C" void kernel_launch(void* const* d_in, const int* in_sizes, int n_in,
                              void* d_out, int out_size)
{
    const int*   gi  = (const int*)  d_in[0];
    const int*   gj  = (const int*)  d_in[1];
    const int*   gk  = (const int*)  d_in[2];
    const float* A   = (const float*)d_in[3];
    const float* Bm  = (const float*)d_in[4];
    const float* Cm  = (const float*)d_in[5];
    const float* W0  = (const float*)d_in[6];
    const float* b0  = (const float*)d_in[7];
    const float* W1  = (const float*)d_in[8];
    const float* b1  = (const float*)d_in[9];
    const float* W2  = (const float*)d_in[10];
    const float* b2  = (const float*)d_in[11];
    const float* W3  = (const float*)d_in[12];
    const float* b3  = (const float*)d_in[13];
    const float* fcw = (const float*)d_in[14];
    const float* fcb = (const float*)d_in[15];
    float* out = (float*)d_out;

    const int batch  = in_sizes[0];
    const int blocks = batch / WPB;
    const size_t smemBytes = (size_t)(2 * WPFL + WPB * SSTR) * sizeof(float);

    cudaFuncSetAttribute(NTC_30202210025785_kernel,
                         cudaFuncAttributeMaxDynamicSharedMemorySize, (int)smemBytes);

    NTC_30202210025785_kernel<<<blocks, THREADS, smemBytes>>>(
        gi, gj, gk, A, Bm, Cm, W0, b0, W1, b1, W2, b2, W3, b3, fcw, fcb, out);
}